// round 13
// baseline (speedup 1.0000x reference)
#include <cuda_runtime.h>
#include <cuda_fp16.h>
#include <math.h>
#include <stdint.h>

#define B_   32
#define S_   512
#define D_   768
#define M_   384
#define H_   8
#define DK_  96
#define BS_  (B_*S_)
#define NM_  (BS_*M_)

#define STG    4
#define PITCH  40                 // halves per smem row (32 + 8 pad = 5x16B)
#define AST    (128*PITCH)        // halves per stage (A or B)
#define GSMEM  (STG*2*AST*2)      // 81920 B

// ---------------- fp32 scratch ----------------
__device__ float g_scores[67108864];   // arena: fp16 scores in first half
__device__ float g_Isem [NM_];
__device__ float g_Hl   [NM_];
__device__ float g_h1   [NM_];
__device__ float g_h2   [NM_];
__device__ float g_rowloss[BS_];
__device__ float g_S    [8*BS_];       // loss partial sums S0..S7
__device__ float g_amf  [BS_];
__device__ float g_smf  [BS_];
__device__ float g_dwf  [BS_];         // dw[s] = a[s]*sm[s]*d12[s]
// ---------------- fp16 scratch ----------------
__device__ __half g_Xh   [BS_*D_];
__device__ __half g_XTh  [BS_*D_];     // [B][D][S]
__device__ __half g_adjmh[B_*S_*S_];
__device__ __half g_Qh   [BS_*D_];
__device__ __half g_Kh   [BS_*D_];
__device__ __half g_adjh [B_*S_*S_];
__device__ __half g_AH1h [BS_*D_];
__device__ __half g_AH2h [BS_*D_];
__device__ __half g_Isemh[NM_];
__device__ __half g_Icomh[NM_];
__device__ __half g_Hlh  [NM_];
__device__ __half g_HTh  [NM_];        // [B][M][S]
__device__ __half g_Th   [BS_*32];
__device__ __half g_Th2  [BS_*32];
__device__ __half g_n1h  [NM_];
__device__ __half g_n2h  [NM_];
// fp16 transposed weights
__device__ __half g_WqT [D_*D_];
__device__ __half g_WkT [D_*D_];
__device__ __half g_sW0T[M_*D_];
__device__ __half g_dW0T[M_*D_];
__device__ __half g_fc4T[M_*D_];
__device__ __half g_sW1T[M_*M_];
__device__ __half g_dW1T[M_*M_];
__device__ __half g_fc3T[M_*M_];
__device__ __half g_fc1T[32*M_];
__device__ __half g_fc2T[M_*32];

// act: 0 none, 1 relu, 2 elu, 3 relu+gate, 4 combine, 5 self-cos loss, 6 cross-cos loss
struct GOp {
    const __half* A; const __half* B; const float* bias;
    float* C32; __half* C16; const float* Eaux; int act;
    float* Sa; float* Sb; float* Sc; float* Sd;
    const float* am; const float* sm; const float* dw;
};

__device__ __forceinline__ void cp16(uint32_t dst, const void* src) {
    asm volatile("cp.async.ca.shared.global [%0], [%1], 16;\n" :: "r"(dst), "l"(src));
}

// =============================================================================
// FP16 tensor GEMM, all-NT, up to 3 fused ops selected by blockIdx.z/zPerOp.
// Tile 128x128, BK=32, 4-stage cp.async, 256 thr, frags via ldmatrix.x4.
// act 5/6: loss-statistic epilogue (atomicAdd partial sums; no C store).
// =============================================================================
__global__ __launch_bounds__(256)
void gemm_f16(GOp o0, GOp o1, GOp o2, int zPerOp,
              int K, int lda, int ldb, int ldc, int N,
              int nInner, long long sAo, long long sAi,
              long long sBo, long long sBi, long long sC, float alpha)
{
    extern __shared__ __half smem[];
    uint32_t sbase = (uint32_t)__cvta_generic_to_shared(smem);
    uint32_t aU = sbase;
    uint32_t bU = sbase + STG * AST * 2;

    int zg = blockIdx.z;
    int op = zg / zPerOp;
    int zi = zg - op * zPerOp;
    GOp o = (op == 0) ? o0 : ((op == 1) ? o1 : o2);

    int zo = zi / nInner, zii = zi - zo * nInner;
    const __half* A  = o.A + (long long)zo * sAo + (long long)zii * sAi;
    const __half* Bm = o.B + (long long)zo * sBo + (long long)zii * sBi;
    int bm = blockIdx.y << 7;
    int bn = blockIdx.x << 7;
    int Nb = N - bn; if (Nb > 128) Nb = 128;

    int tid  = threadIdx.x;
    int lane = tid & 31;
    int wid  = tid >> 5;
    int wm   = wid >> 2;
    int wn   = wid & 3;

    float acc[4][4][4];
#pragma unroll
    for (int i = 0; i < 4; i++)
#pragma unroll
        for (int j = 0; j < 4; j++)
#pragma unroll
            for (int r = 0; r < 4; r++) acc[i][j][r] = 0.f;

    int KT = K >> 5;

    auto issue_load = [&](int stage, int kt) {
        int k0 = kt << 5;
#pragma unroll
        for (int c = 0; c < 2; c++) {
            int ci = tid + (c << 8);
            int row = ci >> 2, kq = ci & 3;
            uint32_t ad = aU + (uint32_t)((stage * AST + row * PITCH + kq * 8) * 2);
            cp16(ad, A + (long long)(bm + row) * lda + k0 + kq * 8);
            uint32_t bd = bU + (uint32_t)((stage * AST + row * PITCH + kq * 8) * 2);
            if (row < Nb) {
                cp16(bd, Bm + (long long)(bn + row) * ldb + k0 + kq * 8);
            } else {
                asm volatile("st.shared.v4.b32 [%0], {%1,%1,%1,%1};\n"
                             :: "r"(bd), "r"(0) : "memory");
            }
        }
        asm volatile("cp.async.commit_group;\n" ::: "memory");
    };

    auto compute = [&](int buf) {
        uint32_t a_base = aU + (uint32_t)(buf * AST * 2);
        uint32_t b_base = bU + (uint32_t)(buf * AST * 2);
#pragma unroll
        for (int ks = 0; ks < 32; ks += 16) {
            uint32_t a[4][4];
#pragma unroll
            for (int mi = 0; mi < 4; mi++) {
                int row = wm * 64 + mi * 16 + (lane & 15);
                uint32_t addr = a_base +
                    (uint32_t)((row * PITCH + ks + ((lane >> 4) << 3)) * 2);
                asm volatile("ldmatrix.sync.aligned.m8n8.x4.shared.b16 {%0,%1,%2,%3}, [%4];"
                             : "=r"(a[mi][0]), "=r"(a[mi][1]), "=r"(a[mi][2]), "=r"(a[mi][3])
                             : "r"(addr));
            }
            uint32_t bf[4][2];
#pragma unroll
            for (int ni2 = 0; ni2 < 2; ni2++) {
                int n = wn * 32 + ni2 * 16 + (lane & 15);
                uint32_t addr = b_base +
                    (uint32_t)((n * PITCH + ks + ((lane >> 4) << 3)) * 2);
                uint32_t r0, r1, r2, r3;
                asm volatile("ldmatrix.sync.aligned.m8n8.x4.shared.b16 {%0,%1,%2,%3}, [%4];"
                             : "=r"(r0), "=r"(r1), "=r"(r2), "=r"(r3) : "r"(addr));
                bf[2 * ni2][0]     = r0;
                bf[2 * ni2 + 1][0] = r1;
                bf[2 * ni2][1]     = r2;
                bf[2 * ni2 + 1][1] = r3;
            }
#pragma unroll
            for (int mi = 0; mi < 4; mi++)
#pragma unroll
                for (int ni = 0; ni < 4; ni++) {
                    asm volatile(
                        "mma.sync.aligned.m16n8k16.row.col.f32.f16.f16.f32 "
                        "{%0,%1,%2,%3}, {%4,%5,%6,%7}, {%8,%9}, {%0,%1,%2,%3};"
                        : "+f"(acc[mi][ni][0]), "+f"(acc[mi][ni][1]),
                          "+f"(acc[mi][ni][2]), "+f"(acc[mi][ni][3])
                        : "r"(a[mi][0]), "r"(a[mi][1]), "r"(a[mi][2]), "r"(a[mi][3]),
                          "r"(bf[ni][0]), "r"(bf[ni][1]));
                }
        }
    };

#pragma unroll
    for (int s = 0; s < STG - 1; s++) {
        if (s < KT) issue_load(s, s);
        else asm volatile("cp.async.commit_group;\n" ::: "memory");
    }

    for (int kt = 0; kt < KT; kt++) {
        asm volatile("cp.async.wait_group %0;\n" :: "n"(STG - 2));
        __syncthreads();
        int nk = kt + STG - 1;
        if (nk < KT) issue_load(nk & (STG - 1), nk);
        else asm volatile("cp.async.commit_group;\n" ::: "memory");
        compute(kt & (STG - 1));
        __syncthreads();
    }

    int g = lane >> 2, q = lane & 3;

    // ---- loss-statistic epilogue (acts 5/6): C never stored ----
    if (o.act >= 5) {
        const float it = 14.2857142857f;
        int zb = zi << 9;                 // batch * 512
        int rr[8], cc[8];
        float am_r[8], sm_r[8], dw_r[8];
        float am_c[8], sm_c[8], dw_c[8];
#pragma unroll
        for (int mi = 0; mi < 4; mi++)
#pragma unroll
            for (int h = 0; h < 2; h++) {
                int ri = mi * 2 + h;
                int r = bm + wm * 64 + mi * 16 + g + h * 8;
                rr[ri] = r;
                am_r[ri] = o.am[zb + r]; sm_r[ri] = o.sm[zb + r]; dw_r[ri] = o.dw[zb + r];
            }
#pragma unroll
        for (int ni = 0; ni < 4; ni++)
#pragma unroll
            for (int j = 0; j < 2; j++) {
                int ci = ni * 2 + j;
                int c = bn + wn * 32 + ni * 8 + 2 * q + j;
                cc[ci] = c;
                am_c[ci] = o.am[zb + c]; sm_c[ci] = o.sm[zb + c]; dw_c[ci] = o.dw[zb + c];
            }
        float rsA[8], rsB[8], csC[8], csD[8];
#pragma unroll
        for (int i = 0; i < 8; i++) { rsA[i] = 0.f; rsB[i] = 0.f; csC[i] = 0.f; csD[i] = 0.f; }
#pragma unroll
        for (int mi = 0; mi < 4; mi++)
#pragma unroll
            for (int ni = 0; ni < 4; ni++)
#pragma unroll
                for (int v = 0; v < 4; v++) {
                    int h = v >> 1, j = v & 1;
                    int ri = mi * 2 + h, ci = ni * 2 + j;
                    float val = acc[mi][ni][h * 2 + j];
                    bool nd = (rr[ri] != cc[ci]);
                    if (o.act == 5) {
                        if (nd) {
                            rsA[ri] += __expf(am_r[ri] * val * it);
                            rsB[ri] += __expf(am_r[ri] * sm_c[ci] * val * it);
                        }
                    } else {
                        rsA[ri] += __expf(am_r[ri] * val * it);            // S1 (full)
                        csC[ci] += __expf(am_c[ci] * val * it);            // S5 (full)
                        if (nd) {
                            rsB[ri] += __expf(am_r[ri] * sm_c[ci] * val * dw_r[ri] * it);  // S3
                            csD[ci] += __expf(am_c[ci] * sm_r[ri] * val * dw_c[ci] * it);  // S7
                        }
                    }
                }
#pragma unroll
        for (int i = 0; i < 8; i++) {
            atomicAdd(&o.Sa[zb + rr[i]], rsA[i]);
            atomicAdd(&o.Sb[zb + rr[i]], rsB[i]);
        }
        if (o.act == 6) {
#pragma unroll
            for (int i = 0; i < 8; i++) {
                atomicAdd(&o.Sc[zb + cc[i]], csC[i]);
                atomicAdd(&o.Sd[zb + cc[i]], csD[i]);
            }
        }
        return;
    }

    // ---- standard epilogue ----
    long long cz = (long long)zi * sC;
#pragma unroll
    for (int mi = 0; mi < 4; mi++) {
#pragma unroll
        for (int ni = 0; ni < 4; ni++) {
            int col = bn + wn * 32 + ni * 8 + 2 * q;
            if (col >= N) continue;
            float bb0 = o.bias ? o.bias[col]     : 0.f;
            float bb1 = o.bias ? o.bias[col + 1] : 0.f;
#pragma unroll
            for (int half_ = 0; half_ < 2; half_++) {
                int r = bm + wm * 64 + mi * 16 + g + half_ * 8;
                long long off = cz + (long long)r * ldc + col;
                float v0 = acc[mi][ni][half_ * 2 + 0] * alpha + bb0;
                float v1 = acc[mi][ni][half_ * 2 + 1] * alpha + bb1;
                if (o.act == 1) { v0 = fmaxf(v0, 0.f); v1 = fmaxf(v1, 0.f); }
                else if (o.act == 2) {
                    v0 = v0 > 0.f ? v0 : (__expf(v0) - 1.f);
                    v1 = v1 > 0.f ? v1 : (__expf(v1) - 1.f);
                } else if (o.act == 3) {
                    v0 = fmaxf(v0, 0.f); v1 = fmaxf(v1, 0.f);
                    float2 e = *reinterpret_cast<const float2*>(o.Eaux + off);
                    float g0 = 1.f / (1.f + __expf(-e.x));
                    float g1 = 1.f / (1.f + __expf(-e.y));
                    v0 = g0 * v0 + (1.f - g0) * e.x;
                    v1 = g1 * v1 + (1.f - g1) * e.y;
                } else if (o.act == 4) {
                    float2 e = *reinterpret_cast<const float2*>(o.Eaux + off);
                    float g0 = 0.6f / (1.f + __expf(-v0));
                    float g1 = 0.6f / (1.f + __expf(-v1));
                    v0 = (1.f - g0) * e.x + g0 * v0;
                    v1 = (1.f - g1) * e.y + g1 * v1;
                }
                if (o.C32) {
                    float2 w; w.x = v0; w.y = v1;
                    *reinterpret_cast<float2*>(o.C32 + off) = w;
                }
                if (o.C16) {
                    __half2 h = __floats2half2_rn(v0, v1);
                    *reinterpret_cast<__half2*>(o.C16 + off) = h;
                }
            }
        }
    }
}

// dual-array elementwise fp32 -> fp16 (both n % 4 == 0)
__global__ void conv16b(const float* __restrict__ in1, __half* __restrict__ out1, int n41,
                        const float* __restrict__ in2, __half* __restrict__ out2, int n42)
{
    int i = blockIdx.x * blockDim.x + threadIdx.x;
    int stride = gridDim.x * blockDim.x;
    int tot = n41 + n42;
    for (; i < tot; i += stride) {
        const float* in; __half* out; int j;
        if (i < n41) { in = in1; out = out1; j = i; }
        else         { in = in2; out = out2; j = i - n41; }
        float4 v = reinterpret_cast<const float4*>(in)[j];
        reinterpret_cast<__half2*>(out)[2 * j]     = __floats2half2_rn(v.x, v.y);
        reinterpret_cast<__half2*>(out)[2 * j + 1] = __floats2half2_rn(v.z, v.w);
    }
}

__global__ void convT16(const float* __restrict__ in, __half* __restrict__ out,
                        int R, int Cc)
{
    __shared__ float t[32][33];
    long long bo = (long long)blockIdx.z * R * Cc;
    const float* ib = in + bo;
    __half* ob = out + bo;
    int c0 = blockIdx.x << 5, r0 = blockIdx.y << 5;
    int tx = threadIdx.x, ty = threadIdx.y;
#pragma unroll
    for (int j = ty; j < 32; j += 8)
        t[j][tx] = ib[(long long)(r0 + j) * Cc + c0 + tx];
    __syncthreads();
#pragma unroll
    for (int j = ty; j < 32; j += 8)
        ob[(long long)(c0 + j) * R + r0 + tx] = __float2half_rn(t[tx][j]);
}

__global__ void convT3(const float* i0, const float* i1, const float* i2,
                       __half* o0, __half* o1, __half* o2, int R, int Cc)
{
    __shared__ float t[32][33];
    int op = blockIdx.z;
    const float* ib = (op == 0) ? i0 : ((op == 1) ? i1 : i2);
    __half* ob = (op == 0) ? o0 : ((op == 1) ? o1 : o2);
    int c0 = blockIdx.x << 5, r0 = blockIdx.y << 5;
    int tx = threadIdx.x, ty = threadIdx.y;
#pragma unroll
    for (int j = ty; j < 32; j += 8)
        t[j][tx] = ib[(long long)(r0 + j) * Cc + c0 + tx];
    __syncthreads();
#pragma unroll
    for (int j = ty; j < 32; j += 8)
        ob[(long long)(c0 + j) * R + r0 + tx] = __float2half_rn(t[tx][j]);
}

// =============================================================================
// Masked softmax (fp16 scores) + head mean + diag->1 + row mask -> fp16 adj.
// =============================================================================
__global__ void softmax_mean_kernel(const __half* __restrict__ scores,
                                    const int* __restrict__ attn_mask,
                                    __half* __restrict__ adj)
{
    int s = blockIdx.x, b = blockIdx.y;
    int tid = threadIdx.x;
    int lane = tid & 31, h = tid >> 5;
    __shared__ float accs[512];

    accs[tid] = 0.f; accs[tid + 256] = 0.f;
    __syncthreads();

    const __half* row = scores + ((((long long)b * H_ + h) * S_ + s) << 9);
    const int* cm = attn_mask + b * S_;

    float v[16];
    float mx = -INFINITY;
#pragma unroll
    for (int j = 0; j < 16; j++) {
        int c = lane + (j << 5);
        float x = __half2float(row[c]);
        if (cm[c] == 0) x = -10000.f;
        v[j] = x;
        mx = fmaxf(mx, x);
    }
#pragma unroll
    for (int o = 16; o > 0; o >>= 1) mx = fmaxf(mx, __shfl_xor_sync(0xffffffffu, mx, o));

    float sum = 0.f;
#pragma unroll
    for (int j = 0; j < 16; j++) { v[j] = __expf(v[j] - mx); sum += v[j]; }
#pragma unroll
    for (int o = 16; o > 0; o >>= 1) sum += __shfl_xor_sync(0xffffffffu, sum, o);
    float inv = 1.f / sum;

#pragma unroll
    for (int j = 0; j < 16; j++) atomicAdd(&accs[lane + (j << 5)], v[j] * inv);
    __syncthreads();

    float rmask = (float)attn_mask[b * S_ + s];
    long long obase = (((long long)b * S_ + s) << 9);
#pragma unroll
    for (int k = 0; k < 2; k++) {
        int c = tid + (k << 8);
        float val = (c == s) ? 1.f : accs[c] * 0.125f;
        adj[obase + c] = __float2half_rn(val * rmask);
    }
}

// =============================================================================
// Fused: L2-normalize h1,h2 -> fp16 n1,n2; d12 = <n1,n2>; masks + dw arrays.
// One warp per row. grid*block = 32*BS threads (2048 x 256).
// =============================================================================
__global__ void norm2dw(const float* __restrict__ z1, const float* __restrict__ z2,
                        __half* __restrict__ n1, __half* __restrict__ n2,
                        const int* __restrict__ amask, const int* __restrict__ smask,
                        float* __restrict__ amf, float* __restrict__ smf,
                        float* __restrict__ dwf)
{
    int r = (blockIdx.x * blockDim.x + threadIdx.x) >> 5;
    int lane = threadIdx.x & 31;
    if (r >= BS_) return;
    const float* z1r = z1 + (long long)r * M_;
    const float* z2r = z2 + (long long)r * M_;
    float v1[12], v2[12];
    float ss1 = 0.f, ss2 = 0.f;
#pragma unroll
    for (int j = 0; j < 12; j++) {
        int c = lane + (j << 5);
        v1[j] = z1r[c]; v2[j] = z2r[c];
        ss1 += v1[j] * v1[j]; ss2 += v2[j] * v2[j];
    }
#pragma unroll
    for (int o = 16; o > 0; o >>= 1) {
        ss1 += __shfl_xor_sync(0xffffffffu, ss1, o);
        ss2 += __shfl_xor_sync(0xffffffffu, ss2, o);
    }
    float inv1 = 1.f / fmaxf(sqrtf(ss1), 1e-12f);
    float inv2 = 1.f / fmaxf(sqrtf(ss2), 1e-12f);
    __half* o1 = n1 + (long long)r * M_;
    __half* o2 = n2 + (long long)r * M_;
    float d = 0.f;
#pragma unroll
    for (int j = 0; j < 12; j++) {
        int c = lane + (j << 5);
        __half h1 = __float2half_rn(v1[j] * inv1);
        __half h2 = __float2half_rn(v2[j] * inv2);
        o1[c] = h1; o2[c] = h2;
        d += __half2float(h1) * __half2float(h2);
    }
#pragma unroll
    for (int o = 16; o > 0; o >>= 1) d += __shfl_xor_sync(0xffffffffu, d, o);
    if (lane == 0) {
        float a = (float)amask[r], s = (float)smask[r];
        amf[r] = a; smf[r] = s;
        dwf[r] = a * s * d;
    }
}

__global__ void zero_k(float* __restrict__ p, int n)
{
    int i = blockIdx.x * blockDim.x + threadIdx.x;
    int stride = gridDim.x * blockDim.x;
    for (; i < n; i += stride) p[i] = 0.f;
}

// rowloss from partial sums. grid 64 x 256.
__global__ void rowloss_k(const float* __restrict__ Ssum, const float* __restrict__ dwf,
                          float* __restrict__ rowloss)
{
    int idx = blockIdx.x * blockDim.x + threadIdx.x;
    const float it = 14.2857142857f;
    float ed = __expf(dwf[idx] * it);
    float S0 = Ssum[idx], S1 = Ssum[BS_ + idx], S2 = Ssum[2*BS_ + idx], S3 = Ssum[3*BS_ + idx];
    float S4 = Ssum[4*BS_ + idx], S5 = Ssum[5*BS_ + idx], S6 = Ssum[6*BS_ + idx], S7 = Ssum[7*BS_ + idx];
    float l1 = -__logf((ed + S2 + S3) / (S0 + S1));
    float l2 = -__logf((ed + S6 + S7) / (S4 + S5));
    rowloss[idx] = 0.5f * (l1 + l2);
}

__global__ void final_reduce_kernel(const float* __restrict__ rl, float* __restrict__ out)
{
    __shared__ float red[32];
    int tid = threadIdx.x;
    float s = 0.f;
    for (int i = tid; i < BS_; i += 1024) s += rl[i];
#pragma unroll
    for (int o = 16; o > 0; o >>= 1) s += __shfl_xor_sync(0xffffffffu, s, o);
    if ((tid & 31) == 0) red[tid >> 5] = s;
    __syncthreads();
    if (tid < 32) {
        float x = red[tid];
#pragma unroll
        for (int o = 16; o > 0; o >>= 1) x += __shfl_xor_sync(0xffffffffu, x, o);
        if (tid == 0) out[0] = x / (float)BS_;
    }
}

// =============================================================================
extern "C" void kernel_launch(void* const* d_in, const int* in_sizes, int n_in,
                              void* d_out, int out_size)
{
    const float* X     = (const float*)d_in[0];
    const float* adjm  = (const float*)d_in[1];
    const int*   amask = (const int*)d_in[2];
    const int*   smsk  = (const int*)d_in[3];
    const int*   amsk  = (const int*)d_in[4];
    const float* Wq    = (const float*)d_in[5];
    const float* bq    = (const float*)d_in[6];
    const float* Wk    = (const float*)d_in[7];
    const float* bk    = (const float*)d_in[8];
    const float* semW0 = (const float*)d_in[9];
    const float* semb0 = (const float*)d_in[10];
    const float* semW1 = (const float*)d_in[11];
    const float* semb1 = (const float*)d_in[12];
    const float* depW0 = (const float*)d_in[13];
    const float* depb0 = (const float*)d_in[14];
    const float* depW1 = (const float*)d_in[15];
    const float* depb1 = (const float*)d_in[16];
    const float* fc1W  = (const float*)d_in[17];
    const float* fc1b  = (const float*)d_in[18];
    const float* fc2W  = (const float*)d_in[19];
    const float* fc2b  = (const float*)d_in[20];
    const float* fc3W  = (const float*)d_in[21];
    const float* fc3b  = (const float*)d_in[22];
    const float* fc4W  = (const float*)d_in[23];
    const float* fc4b  = (const float*)d_in[24];
    float* out = (float*)d_out;

    cudaFuncSetAttribute(gemm_f16, cudaFuncAttributeMaxDynamicSharedMemorySize, GSMEM);

    float *pS, *pIsem, *pHl, *ph1, *ph2, *pRL, *pSs, *pAmf, *pSmf, *pDwf;
    __half *Xh, *XTh, *adjmh, *Qh, *Kh, *adjh, *AH1h, *AH2h, *Isemh, *Icomh,
           *Hlh, *HTh, *Th, *Th2, *n1h, *n2h,
           *WqT, *WkT, *sW0T, *dW0T, *fc4T, *sW1T, *dW1T, *fc3T, *fc1T, *fc2T;
    cudaGetSymbolAddress((void**)&pS, g_scores);
    cudaGetSymbolAddress((void**)&pIsem, g_Isem);
    cudaGetSymbolAddress((void**)&pHl, g_Hl);
    cudaGetSymbolAddress((void**)&ph1, g_h1);
    cudaGetSymbolAddress((void**)&ph2, g_h2);
    cudaGetSymbolAddress((void**)&pRL, g_rowloss);
    cudaGetSymbolAddress((void**)&pSs, g_S);
    cudaGetSymbolAddress((void**)&pAmf, g_amf);
    cudaGetSymbolAddress((void**)&pSmf, g_smf);
    cudaGetSymbolAddress((void**)&pDwf, g_dwf);
    cudaGetSymbolAddress((void**)&Xh, g_Xh);
    cudaGetSymbolAddress((void**)&XTh, g_XTh);
    cudaGetSymbolAddress((void**)&adjmh, g_adjmh);
    cudaGetSymbolAddress((void**)&Qh, g_Qh);
    cudaGetSymbolAddress((void**)&Kh, g_Kh);
    cudaGetSymbolAddress((void**)&adjh, g_adjh);
    cudaGetSymbolAddress((void**)&AH1h, g_AH1h);
    cudaGetSymbolAddress((void**)&AH2h, g_AH2h);
    cudaGetSymbolAddress((void**)&Isemh, g_Isemh);
    cudaGetSymbolAddress((void**)&Icomh, g_Icomh);
    cudaGetSymbolAddress((void**)&Hlh, g_Hlh);
    cudaGetSymbolAddress((void**)&HTh, g_HTh);
    cudaGetSymbolAddress((void**)&Th, g_Th);
    cudaGetSymbolAddress((void**)&Th2, g_Th2);
    cudaGetSymbolAddress((void**)&n1h, g_n1h);
    cudaGetSymbolAddress((void**)&n2h, g_n2h);
    cudaGetSymbolAddress((void**)&WqT, g_WqT);
    cudaGetSymbolAddress((void**)&WkT, g_WkT);
    cudaGetSymbolAddress((void**)&sW0T, g_sW0T);
    cudaGetSymbolAddress((void**)&dW0T, g_dW0T);
    cudaGetSymbolAddress((void**)&fc4T, g_fc4T);
    cudaGetSymbolAddress((void**)&sW1T, g_sW1T);
    cudaGetSymbolAddress((void**)&dW1T, g_dW1T);
    cudaGetSymbolAddress((void**)&fc3T, g_fc3T);
    cudaGetSymbolAddress((void**)&fc1T, g_fc1T);
    cudaGetSymbolAddress((void**)&fc2T, g_fc2T);

    __half* scoresh = (__half*)pS;
    float* S0 = pSs;            float* S1 = pSs + BS_;
    float* S2 = pSs + 2*BS_;    float* S3 = pSs + 3*BS_;
    float* S4 = pSs + 4*BS_;    float* S5 = pSs + 5*BS_;
    float* S6 = pSs + 6*BS_;    float* S7 = pSs + 7*BS_;

    const long long SS = (long long)S_ * S_;
    const long long SD = (long long)S_ * D_;
    const long long SM = (long long)S_ * M_;
    dim3 tb(32, 8);
    GOp nop = {nullptr, nullptr, nullptr, nullptr, nullptr, nullptr, 0,
               nullptr, nullptr, nullptr, nullptr, nullptr, nullptr, nullptr};

    // ---- conversions + zeroing loss sums ----
    conv16b<<<4096, 256>>>(X, Xh, BS_ * D_ / 4, adjm, adjmh, B_ * S_ * S_ / 4);
    zero_k<<<128, 256>>>(pSs, 8 * BS_);
    convT16<<<dim3(24, 16, B_), tb>>>(X, XTh, S_, D_);
    convT3<<<dim3(24, 24, 2), tb>>>(Wq, Wk, Wk, WqT, WkT, WkT, D_, D_);
    convT3<<<dim3(12, 24, 3), tb>>>(semW0, depW0, fc4W, sW0T, dW0T, fc4T, D_, M_);
    convT3<<<dim3(12, 12, 3), tb>>>(semW1, depW1, fc3W, sW1T, dW1T, fc3T, M_, M_);
    convT3<<<dim3(1, 12, 1), tb>>>(fc1W, fc1W, fc1W, fc1T, fc1T, fc1T, M_, 32);
    convT3<<<dim3(12, 1, 1), tb>>>(fc2W, fc2W, fc2W, fc2T, fc2T, fc2T, 32, M_);

    // ---- {Q,K} projections, merged ----
    {
        GOp q = nop; q.A = Xh; q.B = WqT; q.bias = bq; q.C16 = Qh;
        GOp k = nop; k.A = Xh; k.B = WkT; k.bias = bk; k.C16 = Kh;
        gemm_f16<<<dim3(6, 128, 2), 256, GSMEM>>>(q, k, nop, 1,
            D_, D_, D_, D_, D_, 1, 0, 0, 0, 0, 0, 1.f);
    }
    // ---- per-head scores -> fp16 ----
    {
        GOp sop = nop; sop.A = Qh; sop.B = Kh; sop.C16 = scoresh;
        gemm_f16<<<dim3(4, 4, 256), 256, GSMEM>>>(sop, nop, nop, 256,
            DK_, D_, D_, S_, S_, H_, SD, DK_, SD, DK_, SS, 1.0f / sqrtf((float)DK_));
    }
    softmax_mean_kernel<<<dim3(S_, B_), 256>>>(scoresh, amask, adjh);

    // ---- Layer 0 ----
    {
        GOp a1 = nop; a1.A = adjh;  a1.B = XTh; a1.C16 = AH1h;
        GOp a2 = nop; a2.A = adjmh; a2.B = XTh; a2.C16 = AH2h;
        gemm_f16<<<dim3(6, 4, 64), 256, GSMEM>>>(a1, a2, nop, 32,
            S_, S_, S_, D_, D_, 1, SS, 0, SD, 0, SD, 1.f);
    }
    {
        GOp sw = nop; sw.A = AH1h; sw.B = sW0T; sw.bias = semb0; sw.C32 = pIsem; sw.C16 = Isemh;
        GOp f4 = nop; f4.A = Xh;   f4.B = fc4T; f4.bias = fc4b;  f4.C32 = pHl;
        gemm_f16<<<dim3(3, 128, 2), 256, GSMEM>>>(sw, f4, nop, 1,
            D_, D_, D_, M_, M_, 1, 0, 0, 0, 0, 0, 1.f);
    }
    {
        GOp dw = nop; dw.A = AH2h; dw.B = dW0T; dw.bias = depb0; dw.C16 = Icomh;
        dw.Eaux = pIsem; dw.act = 4;
        gemm_f16<<<dim3(3, 128, 1), 256, GSMEM>>>(dw, nop, nop, 1,
            D_, D_, D_, M_, M_, 1, 0, 0, 0, 0, 0, 1.f);
    }
    {
        GOp f3 = nop; f3.A = Icomh; f3.B = fc3T; f3.bias = fc3b;
        f3.C32 = pHl; f3.C16 = Hlh; f3.Eaux = pHl; f3.act = 3;
        gemm_f16<<<dim3(3, 128, 1), 256, GSMEM>>>(f3, nop, nop, 1,
            M_, M_, M_, M_, M_, 1, 0, 0, 0, 0, 0, 1.f);
    }
    convT16<<<dim3(12, 16, B_), tb>>>(pHl, HTh, S_, M_);

    // ---- Layer 1 ----
    {
        GOp a1 = nop; a1.A = adjh;  a1.B = HTh; a1.C16 = AH1h;
        GOp a2 = nop; a2.A = adjmh; a2.B = HTh; a2.C16 = AH2h;
        gemm_f16<<<dim3(3, 4, 64), 256, GSMEM>>>(a1, a2, nop, 32,
            S_, S_, S_, M_, M_, 1, SS, 0, SM, 0, SM, 1.f);
    }
    {
        GOp sw = nop; sw.A = AH1h; sw.B = sW1T; sw.bias = semb1; sw.C32 = pIsem; sw.C16 = Isemh;
        gemm_f16<<<dim3(3, 128, 1), 256, GSMEM>>>(sw, nop, nop, 1,
            M_, M_, M_, M_, M_, 1, 0, 0, 0, 0, 0, 1.f);
    }
    {
        GOp dw = nop; dw.A = AH2h; dw.B = dW1T; dw.bias = depb1; dw.C16 = Icomh;
        dw.Eaux = pIsem; dw.act = 4;
        gemm_f16<<<dim3(3, 128, 1), 256, GSMEM>>>(dw, nop, nop, 1,
            M_, M_, M_, M_, M_, 1, 0, 0, 0, 0, 0, 1.f);
    }
    {
        GOp f3 = nop; f3.A = Icomh; f3.B = fc3T; f3.bias = fc3b;
        f3.C32 = pHl; f3.C16 = Hlh; f3.Eaux = pHl; f3.act = 3;
        gemm_f16<<<dim3(3, 128, 1), 256, GSMEM>>>(f3, nop, nop, 1,
            M_, M_, M_, M_, M_, 1, 0, 0, 0, 0, 0, 1.f);
    }

    // ---- projection head ----
    {
        GOp p1 = nop; p1.A = Hlh;   p1.B = fc1T; p1.bias = fc1b; p1.C16 = Th;  p1.act = 2;
        GOp p2 = nop; p2.A = Isemh; p2.B = fc1T; p2.bias = fc1b; p2.C16 = Th2; p2.act = 2;
        gemm_f16<<<dim3(1, 128, 2), 256, GSMEM>>>(p1, p2, nop, 1,
            M_, M_, M_, 32, 32, 1, 0, 0, 0, 0, 0, 1.f);
    }
    {
        GOp p1 = nop; p1.A = Th;  p1.B = fc2T; p1.bias = fc2b; p1.C32 = ph1;
        GOp p2 = nop; p2.A = Th2; p2.B = fc2T; p2.bias = fc2b; p2.C32 = ph2;
        gemm_f16<<<dim3(3, 128, 2), 256, GSMEM>>>(p1, p2, nop, 1,
            32, 32, 32, M_, M_, 1, 0, 0, 0, 0, 0, 1.f);
    }

    // ---- normalize + d12/dw/masks prepass ----
    norm2dw<<<2048, 256>>>(ph1, ph2, n1h, n2h, amsk, smsk, pAmf, pSmf, pDwf);

    // ---- cosine GEMMs with fused loss-statistic epilogues ----
    {
        GOp c1 = nop; c1.A = n1h; c1.B = n1h; c1.act = 5;
        c1.Sa = S0; c1.Sb = S2; c1.am = pAmf; c1.sm = pSmf; c1.dw = pDwf;
        GOp c2 = nop; c2.A = n1h; c2.B = n2h; c2.act = 6;
        c2.Sa = S1; c2.Sb = S3; c2.Sc = S5; c2.Sd = S7;
        c2.am = pAmf; c2.sm = pSmf; c2.dw = pDwf;
        GOp c3 = nop; c3.A = n2h; c3.B = n2h; c3.act = 5;
        c3.Sa = S4; c3.Sb = S6; c3.am = pAmf; c3.sm = pSmf; c3.dw = pDwf;
        gemm_f16<<<dim3(4, 4, 96), 256, GSMEM>>>(c1, c2, c3, 32,
            M_, M_, M_, S_, S_, 1, SM, 0, SM, 0, SS, 1.f);
    }

    rowloss_k<<<64, 256>>>(pSs, pDwf, pRL);
    final_reduce_kernel<<<1, 1024>>>(pRL, out);
}

// round 17
// speedup vs baseline: 1.3105x; 1.3105x over previous
#include <cuda_runtime.h>
#include <cuda_fp16.h>
#include <math.h>
#include <stdint.h>

#define B_   32
#define S_   512
#define D_   768
#define M_   384
#define H_   8
#define DK_  96
#define BS_  (B_*S_)
#define NM_  (BS_*M_)

#define STG    4
#define PITCH  40                 // halves per smem row (32 + 8 pad = 5x16B)
#define AST    (128*PITCH)        // halves per stage (A or B)
#define GSMEM  (STG*2*AST*2)      // 81920 B

// ---------------- fp32 scratch ----------------
__device__ float g_scores[67108864];   // 268MB arena: fp16 scores + fp16 C matrices
__device__ float g_Isem [NM_];
__device__ float g_Hl   [NM_];
__device__ float g_h1   [NM_];
__device__ float g_h2   [NM_];
__device__ float g_rowloss[BS_];
// ---------------- fp16 scratch ----------------
__device__ __half g_Xh   [BS_*D_];
__device__ __half g_XTh  [BS_*D_];     // [B][D][S]
__device__ __half g_adjmh[B_*S_*S_];
__device__ __half g_Qh   [BS_*D_];
__device__ __half g_Kh   [BS_*D_];
__device__ __half g_adjh [B_*S_*S_];
__device__ __half g_AH1h [BS_*D_];
__device__ __half g_AH2h [BS_*D_];
__device__ __half g_Isemh[NM_];
__device__ __half g_Icomh[NM_];
__device__ __half g_Hlh  [NM_];
__device__ __half g_HTh  [NM_];        // [B][M][S]
__device__ __half g_Th   [BS_*32];
__device__ __half g_Th2  [BS_*32];
__device__ __half g_n1h  [NM_];
__device__ __half g_n2h  [NM_];
// fp16 transposed weights
__device__ __half g_WqT [D_*D_];
__device__ __half g_WkT [D_*D_];
__device__ __half g_sW0T[M_*D_];
__device__ __half g_dW0T[M_*D_];
__device__ __half g_fc4T[M_*D_];
__device__ __half g_sW1T[M_*M_];
__device__ __half g_dW1T[M_*M_];
__device__ __half g_fc3T[M_*M_];
__device__ __half g_fc1T[32*M_];
__device__ __half g_fc2T[M_*32];

struct GOp {
    const __half* A; const __half* B; const float* bias;
    float* C32; __half* C16; const float* Eaux; int act;
};

__device__ __forceinline__ void cp16(uint32_t dst, const void* src) {
    asm volatile("cp.async.ca.shared.global [%0], [%1], 16;\n" :: "r"(dst), "l"(src));
}

// =============================================================================
// FP16 tensor GEMM, all-NT, up to 3 fused ops selected by blockIdx.z/zPerOp.
//   C[op][zi][m,n] = epi(alpha * sum_k A[m,k]*B[n,k] + bias[n])
// Tile 128x128, BK=32, 4-stage cp.async, 256 thr. A- and B-frags via ldmatrix.x4.
// act: 0 none, 1 relu, 2 elu, 3 relu+gate(Eaux, into C32 in-place), 4 combine(Eaux)
// =============================================================================
__global__ __launch_bounds__(256)
void gemm_f16(GOp o0, GOp o1, GOp o2, int zPerOp,
              int K, int lda, int ldb, int ldc, int N,
              int nInner, long long sAo, long long sAi,
              long long sBo, long long sBi, long long sC, float alpha)
{
    extern __shared__ __half smem[];
    uint32_t sbase = (uint32_t)__cvta_generic_to_shared(smem);
    uint32_t aU = sbase;
    uint32_t bU = sbase + STG * AST * 2;

    int zg = blockIdx.z;
    int op = zg / zPerOp;
    int zi = zg - op * zPerOp;
    GOp o = (op == 0) ? o0 : ((op == 1) ? o1 : o2);

    int zo = zi / nInner, zii = zi - zo * nInner;
    const __half* A  = o.A + (long long)zo * sAo + (long long)zii * sAi;
    const __half* Bm = o.B + (long long)zo * sBo + (long long)zii * sBi;
    int bm = blockIdx.y << 7;
    int bn = blockIdx.x << 7;
    int Nb = N - bn; if (Nb > 128) Nb = 128;

    int tid  = threadIdx.x;
    int lane = tid & 31;
    int wid  = tid >> 5;
    int wm   = wid >> 2;
    int wn   = wid & 3;

    float acc[4][4][4];
#pragma unroll
    for (int i = 0; i < 4; i++)
#pragma unroll
        for (int j = 0; j < 4; j++)
#pragma unroll
            for (int r = 0; r < 4; r++) acc[i][j][r] = 0.f;

    int KT = K >> 5;

    auto issue_load = [&](int stage, int kt) {
        int k0 = kt << 5;
#pragma unroll
        for (int c = 0; c < 2; c++) {
            int ci = tid + (c << 8);
            int row = ci >> 2, kq = ci & 3;
            uint32_t ad = aU + (uint32_t)((stage * AST + row * PITCH + kq * 8) * 2);
            cp16(ad, A + (long long)(bm + row) * lda + k0 + kq * 8);
            uint32_t bd = bU + (uint32_t)((stage * AST + row * PITCH + kq * 8) * 2);
            if (row < Nb) {
                cp16(bd, Bm + (long long)(bn + row) * ldb + k0 + kq * 8);
            } else {
                asm volatile("st.shared.v4.b32 [%0], {%1,%1,%1,%1};\n"
                             :: "r"(bd), "r"(0) : "memory");
            }
        }
        asm volatile("cp.async.commit_group;\n" ::: "memory");
    };

    auto compute = [&](int buf) {
        uint32_t a_base = aU + (uint32_t)(buf * AST * 2);
        uint32_t b_base = bU + (uint32_t)(buf * AST * 2);
#pragma unroll
        for (int ks = 0; ks < 32; ks += 16) {
            uint32_t a[4][4];
#pragma unroll
            for (int mi = 0; mi < 4; mi++) {
                int row = wm * 64 + mi * 16 + (lane & 15);
                uint32_t addr = a_base +
                    (uint32_t)((row * PITCH + ks + ((lane >> 4) << 3)) * 2);
                asm volatile("ldmatrix.sync.aligned.m8n8.x4.shared.b16 {%0,%1,%2,%3}, [%4];"
                             : "=r"(a[mi][0]), "=r"(a[mi][1]), "=r"(a[mi][2]), "=r"(a[mi][3])
                             : "r"(addr));
            }
            uint32_t bf[4][2];
#pragma unroll
            for (int ni2 = 0; ni2 < 2; ni2++) {
                int n = wn * 32 + ni2 * 16 + (lane & 15);
                uint32_t addr = b_base +
                    (uint32_t)((n * PITCH + ks + ((lane >> 4) << 3)) * 2);
                uint32_t r0, r1, r2, r3;
                asm volatile("ldmatrix.sync.aligned.m8n8.x4.shared.b16 {%0,%1,%2,%3}, [%4];"
                             : "=r"(r0), "=r"(r1), "=r"(r2), "=r"(r3) : "r"(addr));
                bf[2 * ni2][0]     = r0;
                bf[2 * ni2 + 1][0] = r1;
                bf[2 * ni2][1]     = r2;
                bf[2 * ni2 + 1][1] = r3;
            }
#pragma unroll
            for (int mi = 0; mi < 4; mi++)
#pragma unroll
                for (int ni = 0; ni < 4; ni++) {
                    asm volatile(
                        "mma.sync.aligned.m16n8k16.row.col.f32.f16.f16.f32 "
                        "{%0,%1,%2,%3}, {%4,%5,%6,%7}, {%8,%9}, {%0,%1,%2,%3};"
                        : "+f"(acc[mi][ni][0]), "+f"(acc[mi][ni][1]),
                          "+f"(acc[mi][ni][2]), "+f"(acc[mi][ni][3])
                        : "r"(a[mi][0]), "r"(a[mi][1]), "r"(a[mi][2]), "r"(a[mi][3]),
                          "r"(bf[ni][0]), "r"(bf[ni][1]));
                }
        }
    };

#pragma unroll
    for (int s = 0; s < STG - 1; s++) {
        if (s < KT) issue_load(s, s);
        else asm volatile("cp.async.commit_group;\n" ::: "memory");
    }

    for (int kt = 0; kt < KT; kt++) {
        asm volatile("cp.async.wait_group %0;\n" :: "n"(STG - 2));
        __syncthreads();
        int nk = kt + STG - 1;
        if (nk < KT) issue_load(nk & (STG - 1), nk);
        else asm volatile("cp.async.commit_group;\n" ::: "memory");
        compute(kt & (STG - 1));
        __syncthreads();
    }

    // ---- epilogue ----
    int g = lane >> 2, q = lane & 3;
    long long cz = (long long)zi * sC;
#pragma unroll
    for (int mi = 0; mi < 4; mi++) {
#pragma unroll
        for (int ni = 0; ni < 4; ni++) {
            int col = bn + wn * 32 + ni * 8 + 2 * q;
            if (col >= N) continue;
            float bb0 = o.bias ? o.bias[col]     : 0.f;
            float bb1 = o.bias ? o.bias[col + 1] : 0.f;
#pragma unroll
            for (int half_ = 0; half_ < 2; half_++) {
                int r = bm + wm * 64 + mi * 16 + g + half_ * 8;
                long long off = cz + (long long)r * ldc + col;
                float v0 = acc[mi][ni][half_ * 2 + 0] * alpha + bb0;
                float v1 = acc[mi][ni][half_ * 2 + 1] * alpha + bb1;
                if (o.act == 1) { v0 = fmaxf(v0, 0.f); v1 = fmaxf(v1, 0.f); }
                else if (o.act == 2) {
                    v0 = v0 > 0.f ? v0 : (__expf(v0) - 1.f);
                    v1 = v1 > 0.f ? v1 : (__expf(v1) - 1.f);
                } else if (o.act == 3) {
                    v0 = fmaxf(v0, 0.f); v1 = fmaxf(v1, 0.f);
                    float2 e = *reinterpret_cast<const float2*>(o.Eaux + off);
                    float g0 = 1.f / (1.f + __expf(-e.x));
                    float g1 = 1.f / (1.f + __expf(-e.y));
                    v0 = g0 * v0 + (1.f - g0) * e.x;
                    v1 = g1 * v1 + (1.f - g1) * e.y;
                } else if (o.act == 4) {
                    float2 e = *reinterpret_cast<const float2*>(o.Eaux + off);
                    float g0 = 0.6f / (1.f + __expf(-v0));
                    float g1 = 0.6f / (1.f + __expf(-v1));
                    v0 = (1.f - g0) * e.x + g0 * v0;
                    v1 = (1.f - g1) * e.y + g1 * v1;
                }
                if (o.C32) {
                    float2 w; w.x = v0; w.y = v1;
                    *reinterpret_cast<float2*>(o.C32 + off) = w;
                }
                if (o.C16) {
                    __half2 h = __floats2half2_rn(v0, v1);
                    *reinterpret_cast<__half2*>(o.C16 + off) = h;
                }
            }
        }
    }
}

// dual-array elementwise fp32 -> fp16 (both n % 4 == 0)
__global__ void conv16b(const float* __restrict__ in1, __half* __restrict__ out1, int n41,
                        const float* __restrict__ in2, __half* __restrict__ out2, int n42)
{
    int i = blockIdx.x * blockDim.x + threadIdx.x;
    int stride = gridDim.x * blockDim.x;
    int tot = n41 + n42;
    for (; i < tot; i += stride) {
        const float* in; __half* out; int j;
        if (i < n41) { in = in1; out = out1; j = i; }
        else         { in = in2; out = out2; j = i - n41; }
        float4 v = reinterpret_cast<const float4*>(in)[j];
        reinterpret_cast<__half2*>(out)[2 * j]     = __floats2half2_rn(v.x, v.y);
        reinterpret_cast<__half2*>(out)[2 * j + 1] = __floats2half2_rn(v.z, v.w);
    }
}

// batched transpose + convert: out[b][c][r] = (half) in[b][r][c]; z = batch
__global__ void convT16(const float* __restrict__ in, __half* __restrict__ out,
                        int R, int Cc)
{
    __shared__ float t[32][33];
    long long bo = (long long)blockIdx.z * R * Cc;
    const float* ib = in + bo;
    __half* ob = out + bo;
    int c0 = blockIdx.x << 5, r0 = blockIdx.y << 5;
    int tx = threadIdx.x, ty = threadIdx.y;
#pragma unroll
    for (int j = ty; j < 32; j += 8)
        t[j][tx] = ib[(long long)(r0 + j) * Cc + c0 + tx];
    __syncthreads();
#pragma unroll
    for (int j = ty; j < 32; j += 8)
        ob[(long long)(c0 + j) * R + r0 + tx] = __float2half_rn(t[tx][j]);
}

// up to 3 weight transposes in one launch; z selects op (same R, Cc)
__global__ void convT3(const float* i0, const float* i1, const float* i2,
                       __half* o0, __half* o1, __half* o2, int R, int Cc)
{
    __shared__ float t[32][33];
    int op = blockIdx.z;
    const float* ib = (op == 0) ? i0 : ((op == 1) ? i1 : i2);
    __half* ob = (op == 0) ? o0 : ((op == 1) ? o1 : o2);
    int c0 = blockIdx.x << 5, r0 = blockIdx.y << 5;
    int tx = threadIdx.x, ty = threadIdx.y;
#pragma unroll
    for (int j = ty; j < 32; j += 8)
        t[j][tx] = ib[(long long)(r0 + j) * Cc + c0 + tx];
    __syncthreads();
#pragma unroll
    for (int j = ty; j < 32; j += 8)
        ob[(long long)(c0 + j) * R + r0 + tx] = __float2half_rn(t[tx][j]);
}

// fp16 batched transpose (C21 = C12^T)
__global__ void transpose_h(const __half* __restrict__ in, __half* __restrict__ out,
                            int R, int Cc)
{
    __shared__ __half t[32][34];
    long long bo = (long long)blockIdx.z * R * Cc;
    const __half* ib = in + bo;
    __half* ob = out + bo;
    int c0 = blockIdx.x << 5, r0 = blockIdx.y << 5;
    int tx = threadIdx.x, ty = threadIdx.y;
#pragma unroll
    for (int j = ty; j < 32; j += 8)
        t[j][tx] = ib[(long long)(r0 + j) * Cc + c0 + tx];
    __syncthreads();
#pragma unroll
    for (int j = ty; j < 32; j += 8)
        ob[(long long)(c0 + j) * R + r0 + tx] = t[tx][j];
}

// =============================================================================
// Masked softmax over keys (fp16 scores) + mean over heads + diag->1 + row mask.
// =============================================================================
__global__ void softmax_mean_kernel(const __half* __restrict__ scores,
                                    const int* __restrict__ attn_mask,
                                    __half* __restrict__ adj)
{
    int s = blockIdx.x, b = blockIdx.y;
    int tid = threadIdx.x;
    int lane = tid & 31, h = tid >> 5;
    __shared__ float accs[512];

    accs[tid] = 0.f; accs[tid + 256] = 0.f;
    __syncthreads();

    const __half* row = scores + ((((long long)b * H_ + h) * S_ + s) << 9);
    const int* cm = attn_mask + b * S_;

    float v[16];
    float mx = -INFINITY;
#pragma unroll
    for (int j = 0; j < 16; j++) {
        int c = lane + (j << 5);
        float x = __half2float(row[c]);
        if (cm[c] == 0) x = -10000.f;
        v[j] = x;
        mx = fmaxf(mx, x);
    }
#pragma unroll
    for (int o = 16; o > 0; o >>= 1) mx = fmaxf(mx, __shfl_xor_sync(0xffffffffu, mx, o));

    float sum = 0.f;
#pragma unroll
    for (int j = 0; j < 16; j++) { v[j] = __expf(v[j] - mx); sum += v[j]; }
#pragma unroll
    for (int o = 16; o > 0; o >>= 1) sum += __shfl_xor_sync(0xffffffffu, sum, o);
    float inv = 1.f / sum;

#pragma unroll
    for (int j = 0; j < 16; j++) atomicAdd(&accs[lane + (j << 5)], v[j] * inv);
    __syncthreads();

    float rmask = (float)attn_mask[b * S_ + s];
    long long obase = (((long long)b * S_ + s) << 9);
#pragma unroll
    for (int k = 0; k < 2; k++) {
        int c = tid + (k << 8);
        float val = (c == s) ? 1.f : accs[c] * 0.125f;
        adj[obase + c] = __float2half_rn(val * rmask);
    }
}

// Two-tensor row L2-normalize -> fp16. One warp per row.
__global__ void normalize2(const float* __restrict__ z1, __half* __restrict__ o1,
                           const float* __restrict__ z2, __half* __restrict__ o2,
                           int rows, int cols)
{
    int gw = (blockIdx.x * blockDim.x + threadIdx.x) >> 5;
    int lane = threadIdx.x & 31;
    int nw = (gridDim.x * blockDim.x) >> 5;
    for (int r = gw; r < 2 * rows; r += nw) {
        const float* zin = (r < rows) ? z1 : z2;
        __half* zout = (r < rows) ? o1 : o2;
        int rr = (r < rows) ? r : r - rows;
        const float* zr = zin + (long long)rr * cols;
        float ss = 0.f;
        for (int c = lane; c < cols; c += 32) { float v = zr[c]; ss += v * v; }
#pragma unroll
        for (int o = 16; o > 0; o >>= 1) ss += __shfl_xor_sync(0xffffffffu, ss, o);
        float inv = 1.f / fmaxf(sqrtf(ss), 1e-12f);
        __half* orow = zout + (long long)rr * cols;
        for (int c = lane; c < cols; c += 32)
            orow[c] = __float2half_rn(zr[c] * inv);
    }
}

// =============================================================================
// Scope contrastive loss per (b,s); C matrices in fp16. block=(512), grid=(S,B).
// =============================================================================
__global__ void loss_kernel(const __half* __restrict__ C11, const __half* __restrict__ C12,
                            const __half* __restrict__ C21, const __half* __restrict__ C22,
                            const int* __restrict__ s_mask, const int* __restrict__ a_mask,
                            float* __restrict__ rowloss)
{
    int s = blockIdx.x, b = blockIdx.y;
    int t = threadIdx.x;
    int lane = t & 31, wid = t >> 5;
    __shared__ float red8[8][16];
    __shared__ float Ssh[8];

    const float it = 1.f / 0.07f;
    long long base = (((long long)b * S_ + s) << 9);
    long long diag = base + s;

    float a   = (float)a_mask[b * S_ + s];
    float sms = (float)s_mask[b * S_ + s];
    float smt = (float)s_mask[b * S_ + t];

    float d11 = __half2float(C11[diag]), d12 = __half2float(C12[diag]);
    float d21 = __half2float(C21[diag]), d22 = __half2float(C22[diag]);
    float dw1 = a * sms * d12;
    float dw2 = a * sms * d21;

    float c11 = __half2float(C11[base + t]), c12 = __half2float(C12[base + t]);
    float c21 = __half2float(C21[base + t]), c22 = __half2float(C22[base + t]);

    float vals[8];
    vals[0] = __expf(a * c11 * it);
    vals[1] = __expf(a * c12 * it);
    vals[2] = __expf(a * smt * c11 * it);
    vals[3] = __expf(a * smt * c12 * dw1 * it);
    vals[4] = __expf(a * c22 * it);
    vals[5] = __expf(a * c21 * it);
    vals[6] = __expf(a * smt * c22 * it);
    vals[7] = __expf(a * smt * c21 * dw2 * it);

#pragma unroll
    for (int k = 0; k < 8; k++) {
        float v = vals[k];
#pragma unroll
        for (int o = 16; o > 0; o >>= 1) v += __shfl_xor_sync(0xffffffffu, v, o);
        if (lane == 0) red8[k][wid] = v;
    }
    __syncthreads();
    if (t < 8) {
        float x = 0.f;
        for (int w2 = 0; w2 < 16; w2++) x += red8[t][w2];
        Ssh[t] = x;
    }
    __syncthreads();

    if (t == 0) {
        float pos1 = __expf(a * sms * d12 * it)
                   + (Ssh[2] - __expf(a * sms * d11 * it))
                   + (Ssh[3] - __expf(dw1 * dw1 * it));
        float alle1 = Ssh[0] + Ssh[1] - __expf(a * d11 * it);
        float l1v = -__logf(pos1 / alle1);

        float pos2 = __expf(a * sms * d21 * it)
                   + (Ssh[6] - __expf(a * sms * d22 * it))
                   + (Ssh[7] - __expf(dw2 * dw2 * it));
        float alle2 = Ssh[4] + Ssh[5] - __expf(a * d22 * it);
        float l2v = -__logf(pos2 / alle2);

        rowloss[b * S_ + s] = 0.5f * (l1v + l2v);
    }
}

__global__ void final_reduce_kernel(const float* __restrict__ rl, float* __restrict__ out)
{
    __shared__ float red[32];
    int tid = threadIdx.x;
    float s = 0.f;
    for (int i = tid; i < BS_; i += 1024) s += rl[i];
#pragma unroll
    for (int o = 16; o > 0; o >>= 1) s += __shfl_xor_sync(0xffffffffu, s, o);
    if ((tid & 31) == 0) red[tid >> 5] = s;
    __syncthreads();
    if (tid < 32) {
        float x = red[tid];
#pragma unroll
        for (int o = 16; o > 0; o >>= 1) x += __shfl_xor_sync(0xffffffffu, x, o);
        if (tid == 0) out[0] = x / (float)BS_;
    }
}

// =============================================================================
extern "C" void kernel_launch(void* const* d_in, const int* in_sizes, int n_in,
                              void* d_out, int out_size)
{
    const float* X     = (const float*)d_in[0];
    const float* adjm  = (const float*)d_in[1];
    const int*   amask = (const int*)d_in[2];
    const int*   smsk  = (const int*)d_in[3];
    const int*   amsk  = (const int*)d_in[4];
    const float* Wq    = (const float*)d_in[5];
    const float* bq    = (const float*)d_in[6];
    const float* Wk    = (const float*)d_in[7];
    const float* bk    = (const float*)d_in[8];
    const float* semW0 = (const float*)d_in[9];
    const float* semb0 = (const float*)d_in[10];
    const float* semW1 = (const float*)d_in[11];
    const float* semb1 = (const float*)d_in[12];
    const float* depW0 = (const float*)d_in[13];
    const float* depb0 = (const float*)d_in[14];
    const float* depW1 = (const float*)d_in[15];
    const float* depb1 = (const float*)d_in[16];
    const float* fc1W  = (const float*)d_in[17];
    const float* fc1b  = (const float*)d_in[18];
    const float* fc2W  = (const float*)d_in[19];
    const float* fc2b  = (const float*)d_in[20];
    const float* fc3W  = (const float*)d_in[21];
    const float* fc3b  = (const float*)d_in[22];
    const float* fc4W  = (const float*)d_in[23];
    const float* fc4b  = (const float*)d_in[24];
    float* out = (float*)d_out;

    cudaFuncSetAttribute(gemm_f16, cudaFuncAttributeMaxDynamicSharedMemorySize, GSMEM);

    float *pS, *pIsem, *pHl, *ph1, *ph2, *pRL;
    __half *Xh, *XTh, *adjmh, *Qh, *Kh, *adjh, *AH1h, *AH2h, *Isemh, *Icomh,
           *Hlh, *HTh, *Th, *Th2, *n1h, *n2h,
           *WqT, *WkT, *sW0T, *dW0T, *fc4T, *sW1T, *dW1T, *fc3T, *fc1T, *fc2T;
    cudaGetSymbolAddress((void**)&pS, g_scores);
    cudaGetSymbolAddress((void**)&pIsem, g_Isem);
    cudaGetSymbolAddress((void**)&pHl, g_Hl);
    cudaGetSymbolAddress((void**)&ph1, g_h1);
    cudaGetSymbolAddress((void**)&ph2, g_h2);
    cudaGetSymbolAddress((void**)&pRL, g_rowloss);
    cudaGetSymbolAddress((void**)&Xh, g_Xh);
    cudaGetSymbolAddress((void**)&XTh, g_XTh);
    cudaGetSymbolAddress((void**)&adjmh, g_adjmh);
    cudaGetSymbolAddress((void**)&Qh, g_Qh);
    cudaGetSymbolAddress((void**)&Kh, g_Kh);
    cudaGetSymbolAddress((void**)&adjh, g_adjh);
    cudaGetSymbolAddress((void**)&AH1h, g_AH1h);
    cudaGetSymbolAddress((void**)&AH2h, g_AH2h);
    cudaGetSymbolAddress((void**)&Isemh, g_Isemh);
    cudaGetSymbolAddress((void**)&Icomh, g_Icomh);
    cudaGetSymbolAddress((void**)&Hlh, g_Hlh);
    cudaGetSymbolAddress((void**)&HTh, g_HTh);
    cudaGetSymbolAddress((void**)&Th, g_Th);
    cudaGetSymbolAddress((void**)&Th2, g_Th2);
    cudaGetSymbolAddress((void**)&n1h, g_n1h);
    cudaGetSymbolAddress((void**)&n2h, g_n2h);
    cudaGetSymbolAddress((void**)&WqT, g_WqT);
    cudaGetSymbolAddress((void**)&WkT, g_WkT);
    cudaGetSymbolAddress((void**)&sW0T, g_sW0T);
    cudaGetSymbolAddress((void**)&dW0T, g_dW0T);
    cudaGetSymbolAddress((void**)&fc4T, g_fc4T);
    cudaGetSymbolAddress((void**)&sW1T, g_sW1T);
    cudaGetSymbolAddress((void**)&dW1T, g_dW1T);
    cudaGetSymbolAddress((void**)&fc3T, g_fc3T);
    cudaGetSymbolAddress((void**)&fc1T, g_fc1T);
    cudaGetSymbolAddress((void**)&fc2T, g_fc2T);

    // fp16 aliases inside the 268 MB g_scores arena (disjoint lifetimes)
    __half* scoresh = (__half*)pS;
    __half* C11h = (__half*)pS + 67108864LL;
    __half* C12h = C11h + (long long)B_ * S_ * S_;
    __half* C21h = C12h + (long long)B_ * S_ * S_;
    __half* C22h = C21h + (long long)B_ * S_ * S_;

    const long long SS = (long long)S_ * S_;
    const long long SD = (long long)S_ * D_;
    const long long SM = (long long)S_ * M_;
    dim3 tb(32, 8);
    GOp nop = {nullptr, nullptr, nullptr, nullptr, nullptr, nullptr, 0};

    // ---- conversions (merged where shapes match) ----
    conv16b<<<4096, 256>>>(X, Xh, BS_ * D_ / 4, adjm, adjmh, B_ * S_ * S_ / 4);
    convT16<<<dim3(24, 16, B_), tb>>>(X, XTh, S_, D_);
    convT3<<<dim3(24, 24, 2), tb>>>(Wq, Wk, Wk, WqT, WkT, WkT, D_, D_);
    convT3<<<dim3(12, 24, 3), tb>>>(semW0, depW0, fc4W, sW0T, dW0T, fc4T, D_, M_);
    convT3<<<dim3(12, 12, 3), tb>>>(semW1, depW1, fc3W, sW1T, dW1T, fc3T, M_, M_);
    convT3<<<dim3(1, 12, 1), tb>>>(fc1W, fc1W, fc1W, fc1T, fc1T, fc1T, M_, 32);
    convT3<<<dim3(12, 1, 1), tb>>>(fc2W, fc2W, fc2W, fc2T, fc2T, fc2T, 32, M_);

    // ---- {Q,K} projections, merged ----
    {
        GOp q = {Xh, WqT, bq, nullptr, Qh, nullptr, 0};
        GOp k = {Xh, WkT, bk, nullptr, Kh, nullptr, 0};
        gemm_f16<<<dim3(6, 128, 2), 256, GSMEM>>>(q, k, nop, 1,
            D_, D_, D_, D_, D_, 1, 0, 0, 0, 0, 0, 1.f);
    }
    // ---- per-head scores -> fp16 ----
    {
        GOp sop = {Qh, Kh, nullptr, nullptr, scoresh, nullptr, 0};
        gemm_f16<<<dim3(4, 4, 256), 256, GSMEM>>>(sop, nop, nop, 256,
            DK_, D_, D_, S_, S_, H_, SD, DK_, SD, DK_, SS, 1.0f / sqrtf((float)DK_));
    }
    softmax_mean_kernel<<<dim3(S_, B_), 256>>>(scoresh, amask, adjh);

    // ---- Layer 0: {AH_sem, AH_dep} merged ----
    {
        GOp a1 = {adjh,  XTh, nullptr, nullptr, AH1h, nullptr, 0};
        GOp a2 = {adjmh, XTh, nullptr, nullptr, AH2h, nullptr, 0};
        gemm_f16<<<dim3(6, 4, 64), 256, GSMEM>>>(a1, a2, nop, 32,
            S_, S_, S_, D_, D_, 1, SS, 0, SD, 0, SD, 1.f);
    }
    // {semw0, fc4} merged
    {
        GOp sw = {AH1h, sW0T, semb0, pIsem, Isemh, nullptr, 0};
        GOp f4 = {Xh,   fc4T, fc4b,  pHl,   nullptr, nullptr, 0};
        gemm_f16<<<dim3(3, 128, 2), 256, GSMEM>>>(sw, f4, nop, 1,
            D_, D_, D_, M_, M_, 1, 0, 0, 0, 0, 0, 1.f);
    }
    {
        GOp dw = {AH2h, dW0T, depb0, nullptr, Icomh, pIsem, 4};
        gemm_f16<<<dim3(3, 128, 1), 256, GSMEM>>>(dw, nop, nop, 1,
            D_, D_, D_, M_, M_, 1, 0, 0, 0, 0, 0, 1.f);
    }
    {
        GOp f3 = {Icomh, fc3T, fc3b, pHl, Hlh, pHl, 3};
        gemm_f16<<<dim3(3, 128, 1), 256, GSMEM>>>(f3, nop, nop, 1,
            M_, M_, M_, M_, M_, 1, 0, 0, 0, 0, 0, 1.f);
    }
    convT16<<<dim3(12, 16, B_), tb>>>(pHl, HTh, S_, M_);

    // ---- Layer 1 ----
    {
        GOp a1 = {adjh,  HTh, nullptr, nullptr, AH1h, nullptr, 0};
        GOp a2 = {adjmh, HTh, nullptr, nullptr, AH2h, nullptr, 0};
        gemm_f16<<<dim3(3, 4, 64), 256, GSMEM>>>(a1, a2, nop, 32,
            S_, S_, S_, M_, M_, 1, SS, 0, SM, 0, SM, 1.f);
    }
    {
        GOp sw = {AH1h, sW1T, semb1, pIsem, Isemh, nullptr, 0};
        gemm_f16<<<dim3(3, 128, 1), 256, GSMEM>>>(sw, nop, nop, 1,
            M_, M_, M_, M_, M_, 1, 0, 0, 0, 0, 0, 1.f);
    }
    {
        GOp dw = {AH2h, dW1T, depb1, nullptr, Icomh, pIsem, 4};
        gemm_f16<<<dim3(3, 128, 1), 256, GSMEM>>>(dw, nop, nop, 1,
            M_, M_, M_, M_, M_, 1, 0, 0, 0, 0, 0, 1.f);
    }
    {
        GOp f3 = {Icomh, fc3T, fc3b, pHl, Hlh, pHl, 3};
        gemm_f16<<<dim3(3, 128, 1), 256, GSMEM>>>(f3, nop, nop, 1,
            M_, M_, M_, M_, M_, 1, 0, 0, 0, 0, 0, 1.f);
    }

    // ---- projection head ----
    {
        GOp p1 = {Hlh,   fc1T, fc1b, nullptr, Th,  nullptr, 2};
        GOp p2 = {Isemh, fc1T, fc1b, nullptr, Th2, nullptr, 2};
        gemm_f16<<<dim3(1, 128, 2), 256, GSMEM>>>(p1, p2, nop, 1,
            M_, M_, M_, 32, 32, 1, 0, 0, 0, 0, 0, 1.f);
    }
    {
        GOp p1 = {Th,  fc2T, fc2b, ph1, nullptr, nullptr, 0};
        GOp p2 = {Th2, fc2T, fc2b, ph2, nullptr, nullptr, 0};
        gemm_f16<<<dim3(3, 128, 2), 256, GSMEM>>>(p1, p2, nop, 1,
            32, 32, 32, M_, M_, 1, 0, 0, 0, 0, 0, 1.f);
    }

    normalize2<<<2048, 256>>>(ph1, n1h, ph2, n2h, BS_, M_);

    // ---- cosine matrices -> fp16: {C11, C12, C22} merged + fp16 transpose ----
    {
        GOp c1 = {n1h, n1h, nullptr, nullptr, C11h, nullptr, 0};
        GOp c2 = {n1h, n2h, nullptr, nullptr, C12h, nullptr, 0};
        GOp c3 = {n2h, n2h, nullptr, nullptr, C22h, nullptr, 0};
        gemm_f16<<<dim3(4, 4, 96), 256, GSMEM>>>(c1, c2, c3, 32,
            M_, M_, M_, S_, S_, 1, SM, 0, SM, 0, SS, 1.f);
    }
    transpose_h<<<dim3(16, 16, B_), tb>>>(C12h, C21h, S_, S_);

    loss_kernel<<<dim3(S_, B_), 512>>>(C11h, C12h, C21h, C22h, smsk, amsk, pRL);
    final_reduce_kernel<<<1, 1024>>>(pRL, out);
}